// round 17
// baseline (speedup 1.0000x reference)
#include <cuda_runtime.h>
#include <cstdint>

// Problem constants
#define S_LEN 2048
#define B_SZ 4
#define HID 2048
#define T_TOK 8192
#define FF 1408
#define FF2 2816
#define NEXP 8
#define NROWS 16384
#define BK 8

// ---------------- scratch (device globals) ----------------
__device__ int   d_counts[NEXP];
__device__ int   d_offsets[NEXP + 1];
__device__ int   d_cursor[NEXP];
__device__ int   d_ea[T_TOK];
__device__ int   d_eb[T_TOK];
__device__ float d_wa[T_TOK];
__device__ float d_wb[T_TOK];
__device__ int   d_row_token[NROWS];
__device__ int   d_token_pos[T_TOK * 2];
__device__ float d_h[(size_t)NROWS * FF2];
__device__ float d_g[(size_t)NROWS * FF];
__device__ float d_y[(size_t)NROWS * HID];

// ---------------- routing (proven) ----------------
__global__ void zero_counts_kernel() {
    if (threadIdx.x < NEXP) d_counts[threadIdx.x] = 0;
}

__global__ void gate_kernel(const float* __restrict__ x, const float* __restrict__ wg) {
    int t = blockIdx.x;
    const float* xr = x + ((size_t)(t % S_LEN) * B_SZ + (t / S_LEN)) * HID;
    float acc[NEXP];
#pragma unroll
    for (int e = 0; e < NEXP; e++) acc[e] = 0.f;
    for (int h = threadIdx.x; h < HID; h += 256) {
        float xv = xr[h];
#pragma unroll
        for (int e = 0; e < NEXP; e++) acc[e] += xv * wg[e * HID + h];
    }
#pragma unroll
    for (int e = 0; e < NEXP; e++)
        for (int off = 16; off; off >>= 1)
            acc[e] += __shfl_down_sync(0xffffffffu, acc[e], off);
    __shared__ float red[8][NEXP];
    int warp = threadIdx.x >> 5, lane = threadIdx.x & 31;
    if (lane == 0)
#pragma unroll
        for (int e = 0; e < NEXP; e++) red[warp][e] = acc[e];
    __syncthreads();
    if (threadIdx.x == 0) {
        float logits[NEXP];
#pragma unroll
        for (int e = 0; e < NEXP; e++) {
            float s = 0.f;
            for (int w = 0; w < 8; w++) s += red[w][e];
            logits[e] = s;
        }
        float m = logits[0];
#pragma unroll
        for (int e = 1; e < NEXP; e++) m = fmaxf(m, logits[e]);
        float sc[NEXP], Z = 0.f;
#pragma unroll
        for (int e = 0; e < NEXP; e++) { sc[e] = expf(logits[e] - m); Z += sc[e]; }
        float invZ = 1.f / Z;
#pragma unroll
        for (int e = 0; e < NEXP; e++) sc[e] *= invZ;
        int e0 = 0;
#pragma unroll
        for (int e = 1; e < NEXP; e++) if (sc[e] > sc[e0]) e0 = e;
        int e1 = (e0 == 0) ? 1 : 0;
#pragma unroll
        for (int e = 0; e < NEXP; e++) if (e != e0 && sc[e] > sc[e1]) e1 = e;
        float s0 = sc[e0], s1 = sc[e1];
        float inv = 1.f / (s0 + s1 + 1e-20f);
        d_ea[t] = e0; d_eb[t] = e1;
        d_wa[t] = s0 * inv; d_wb[t] = s1 * inv;
        atomicAdd(&d_counts[e0], 1);
        atomicAdd(&d_counts[e1], 1);
    }
}

__global__ void scan_kernel() {
    int o = 0;
    d_offsets[0] = 0;
#pragma unroll
    for (int e = 0; e < NEXP; e++) { o += d_counts[e]; d_offsets[e + 1] = o; }
#pragma unroll
    for (int e = 0; e < NEXP; e++) d_cursor[e] = d_offsets[e];
}

__global__ void assign_kernel() {
    int t = blockIdx.x * blockDim.x + threadIdx.x;
    if (t >= T_TOK) return;
    int p0 = atomicAdd(&d_cursor[d_ea[t]], 1);
    d_row_token[p0] = t;
    d_token_pos[2 * t] = p0;
    int p1 = atomicAdd(&d_cursor[d_eb[t]], 1);
    d_row_token[p1] = t;
    d_token_pos[2 * t + 1] = p1;
}

// ---------------- f32x2 GEMM, double-buffered smem (1 sync/chunk) ----------------
// MODE 0: d_h = gather(x) @ w1e   (K=HID, N=FF2)
// MODE 1: d_y = d_g      @ w2e    (K=FF,  N=HID)
// CTA 128m x 128n, BK=8, 128 threads, micro-tile 8m x 16n. R15/R16 fragment scheme.
// Schedule per chunk: STS(buf) -> sync -> LDG(next) -> compute(buf).
template <int MODE>
__global__ void __launch_bounds__(128, 2)
gemm2x_kernel(const float* __restrict__ Xin, const float* __restrict__ Wbase) {
    constexpr int Kd = (MODE == 0) ? HID : FF;
    constexpr int Nd = (MODE == 0) ? FF2 : HID;
    constexpr int NC = Kd / BK;

    int e = blockIdx.z;
    int seg0 = d_offsets[e], seg1 = d_offsets[e + 1];
    int row0 = seg0 + blockIdx.x * 128;
    if (row0 >= seg1) return;
    int col0 = blockIdx.y * 128;

    __shared__ __align__(16) float2 As2[2][BK][144];   // 2 x 9216 B
    __shared__ __align__(16) float2 Bp[2][BK][80];     // 2 x 5120 B

    int tid = threadIdx.x;
    int tx = tid & 7, ty = tid >> 3;

    const float* W = Wbase + (size_t)e * Kd * Nd + col0;

    int grow = row0 + tid;
    bool a_valid = grow < seg1;
    int asrc = a_valid ? grow : (seg1 - 1);
    const float* Arow;
    if (MODE == 0) {
        int t = d_row_token[asrc];
        Arow = Xin + ((size_t)(t % S_LEN) * B_SZ + (t / S_LEN)) * HID;
    } else {
        Arow = d_g + (size_t)asrc * Kd;
    }
    int pa = tid + 2 * (tid >> 4);
    int abase = ty * 8 + 2 * (ty >> 1);
    int bbase = tx * 10;

    // per-thread B load slots (fixed across chunks): 8 rows x 128 cols = 2 float4/thr
    int bidx[2], brow[2], bcol[2];
#pragma unroll
    for (int q = 0; q < 2; q++) {
        bidx[q] = q * 128 + tid;
        brow[q] = bidx[q] >> 5;
        bcol[q] = (bidx[q] & 31) * 4;
    }

    unsigned long long acc2[8][8];
#pragma unroll
    for (int i = 0; i < 8; i++)
#pragma unroll
        for (int j = 0; j < 8; j++) acc2[i][j] = 0ull;

    // prefetch chunk 0 into registers
    float4 rA[2], rB[2];
#pragma unroll
    for (int c = 0; c < 2; c++)
        rA[c] = a_valid ? *(const float4*)(Arow + c * 4)
                        : make_float4(0.f, 0.f, 0.f, 0.f);
#pragma unroll
    for (int q = 0; q < 2; q++)
        rB[q] = *(const float4*)(W + (size_t)brow[q] * Nd + bcol[q]);

    for (int i = 0; i < NC; i++) {
        int buf = i & 1;
        // store this chunk's registers (loaded >= one compute-phase ago)
#pragma unroll
        for (int c = 0; c < 2; c++) {
            As2[buf][c * 4 + 0][pa] = make_float2(rA[c].x, rA[c].x);
            As2[buf][c * 4 + 1][pa] = make_float2(rA[c].y, rA[c].y);
            As2[buf][c * 4 + 2][pa] = make_float2(rA[c].z, rA[c].z);
            As2[buf][c * 4 + 3][pa] = make_float2(rA[c].w, rA[c].w);
        }
#pragma unroll
        for (int q = 0; q < 2; q++) {
            int p0 = (bidx[q] & 31) * 2;
            int p1 = p0 + 1;
            Bp[buf][brow[q]][(p0 & 7) * 10 + (p0 >> 3)] = make_float2(rB[q].x, rB[q].y);
            Bp[buf][brow[q]][(p1 & 7) * 10 + (p1 >> 3)] = make_float2(rB[q].z, rB[q].w);
        }
        __syncthreads();

        // issue next chunk's global loads; compute below hides their latency
        if (i + 1 < NC) {
            int k0n = (i + 1) * BK;
#pragma unroll
            for (int c = 0; c < 2; c++)
                rA[c] = a_valid ? *(const float4*)(Arow + k0n + c * 4)
                                : make_float4(0.f, 0.f, 0.f, 0.f);
#pragma unroll
            for (int q = 0; q < 2; q++)
                rB[q] = *(const float4*)(W + (size_t)(k0n + brow[q]) * Nd + bcol[q]);
        }

#pragma unroll
        for (int k = 0; k < BK; k++) {
            unsigned long long av[8], bv[8];
#pragma unroll
            for (int m = 0; m < 4; m++) {
                ulonglong2 ta = *(const ulonglong2*)&As2[buf][k][abase + 2 * m];
                av[2 * m] = ta.x; av[2 * m + 1] = ta.y;
                ulonglong2 tb = *(const ulonglong2*)&Bp[buf][k][bbase + 2 * m];
                bv[2 * m] = tb.x; bv[2 * m + 1] = tb.y;
            }
#pragma unroll
            for (int ii = 0; ii < 8; ii++)
#pragma unroll
                for (int j = 0; j < 8; j++)
                    asm("fma.rn.f32x2 %0, %1, %2, %0;"
                        : "+l"(acc2[ii][j]) : "l"(av[ii]), "l"(bv[j]));
        }
    }

    float* C = (MODE == 0) ? d_h : d_y;
#pragma unroll
    for (int i = 0; i < 8; i++) {
        int gr = row0 + ty * 8 + i;
        if (gr < seg1) {
            float* crow = C + (size_t)gr * Nd + col0;
#pragma unroll
            for (int j = 0; j < 8; j++)
                *(unsigned long long*)(crow + j * 16 + tx * 2) = acc2[i][j];
        }
    }
}

// ---------------- swiglu ----------------
__global__ void swiglu_kernel() {
    int r = blockIdx.x;
    const float* hr = d_h + (size_t)r * FF2;
    float2* gf = (float2*)(d_g + (size_t)r * FF);
    for (int j = threadIdx.x; j < FF / 2; j += 256) {
        float2 a = ((const float2*)hr)[j];
        float2 b = ((const float2*)(hr + FF))[j];
        float y0 = (a.x / (1.f + expf(-a.x))) * b.x;
        float y1 = (a.y / (1.f + expf(-a.y))) * b.y;
        gf[j] = make_float2(y0, y1);
    }
}

// ---------------- combine ----------------
__global__ void combine_kernel(float* __restrict__ out) {
    int v = blockIdx.x * blockDim.x + threadIdx.x;
    const int total = T_TOK * (HID / 4);
    if (v >= total) return;
    int t = v / (HID / 4);
    int h4 = v % (HID / 4);
    int p0 = d_token_pos[2 * t], p1 = d_token_pos[2 * t + 1];
    float wa = d_wa[t], wb = d_wb[t];
    const float4 y0 = *(const float4*)&d_y[(size_t)p0 * HID + h4 * 4];
    const float4 y1 = *(const float4*)&d_y[(size_t)p1 * HID + h4 * 4];
    float4 o;
    o.x = wa * y0.x + wb * y1.x;
    o.y = wa * y0.y + wb * y1.y;
    o.z = wa * y0.z + wb * y1.z;
    o.w = wa * y0.w + wb * y1.w;
    int s = t % S_LEN, b = t / S_LEN;
    *(float4*)&out[((size_t)s * B_SZ + b) * HID + h4 * 4] = o;
}

// ---------------- launch ----------------
extern "C" void kernel_launch(void* const* d_in, const int* in_sizes, int n_in,
                              void* d_out, int out_size) {
    const float* x  = (const float*)d_in[0];
    const float* wg = (const float*)d_in[1];
    const float* w1 = (const float*)d_in[2];
    const float* w2 = (const float*)d_in[3];
    float* out = (float*)d_out;

    zero_counts_kernel<<<1, 32>>>();
    gate_kernel<<<T_TOK, 256>>>(x, wg);
    scan_kernel<<<1, 1>>>();
    assign_kernel<<<T_TOK / 256, 256>>>();

    gemm2x_kernel<0><<<dim3(128, FF2 / 128, NEXP), 128>>>(x, w1);
    swiglu_kernel<<<NROWS, 256>>>();
    gemm2x_kernel<1><<<dim3(128, HID / 128, NEXP), 128>>>(nullptr, w2);
    combine_kernel<<<(T_TOK * (HID / 4)) / 256, 256>>>(out);
}